// round 2
// baseline (speedup 1.0000x reference)
#include <cuda_runtime.h>
#include <cuda_bf16.h>

#define NN 50000
#define EE 800000
#define FK 128          // inner dim (always 128 here)
#define C1 192          // fused agg width pass 1 (128 conv1 + 64 leader)
#define C2 128          // agg width pass 2
#define NC 320          // fused GEMM1 output cols: [W1(128) | Wl(64) | Ws(128)]

// ---------------- scratch (device globals; no allocations allowed) -----------
__device__ float g_deg[NN];
__device__ float g_dinv[NN];
__device__ float g_Wc[FK * NC];          // fused weight [128, 320]
__device__ float g_HS1[NN * C1];         // dinv-scaled GEMM1 output (read-only sources)
__device__ float g_S1[NN * C1];          // accumulator (init = HS1)
__device__ float g_HSELF[NN * C2];       // x@Ws + bs
__device__ float g_HNEW[NN * C2];        // gated fusion
__device__ float g_HS2[NN * C2];         // dinv-scaled GEMM2 output
__device__ float g_S2[NN * C2];          // accumulator

// ---------------- small kernels ---------------------------------------------
__global__ void k_init_deg() {
    int i = blockIdx.x * blockDim.x + threadIdx.x;
    if (i < NN) g_deg[i] = 1.0f;                       // self-loop weight
}

__global__ void k_deg_accum(const int* __restrict__ ei,
                            const float* __restrict__ ew) {
    int e = blockIdx.x * blockDim.x + threadIdx.x;
    if (e < EE) {
        int d = ei[EE + e];
        atomicAdd(&g_deg[d], ew[e]);
    }
}

__global__ void k_dinv() {
    int i = blockIdx.x * blockDim.x + threadIdx.x;
    if (i < NN) {
        float dg = g_deg[i];
        g_dinv[i] = dg > 0.0f ? 1.0f / sqrtf(dg) : 0.0f;
    }
}

__global__ void k_build_wc(const float* __restrict__ W1,
                           const float* __restrict__ Wl,
                           const float* __restrict__ Ws) {
    int idx = blockIdx.x * blockDim.x + threadIdx.x;
    if (idx >= FK * NC) return;
    int k = idx / NC, c = idx % NC;
    float v;
    if (c < 128)       v = W1[k * 128 + c];
    else if (c < 192)  v = Wl[k * 64 + (c - 128)];
    else               v = Ws[k * 128 + (c - 192)];
    g_Wc[idx] = v;
}

// ---------------- GEMM: C = A[M,128] @ B[128,Ncols], fused epilogue ----------
// mode 1: cols<192 -> dinv-scaled dual-store HS1/S1 ; cols>=192 -> +bs -> HSELF
// mode 2: dinv-scaled dual-store HS2/S2
#define BM 64
#define BN 64
#define BK 32
__global__ __launch_bounds__(256) void k_gemm(const float* __restrict__ A,
                                              const float* __restrict__ B,
                                              int M, int Ncols, int mode,
                                              const float* __restrict__ bs) {
    __shared__ float As[BK][BM + 1];
    __shared__ float Bs[BK][BN];
    int bm = blockIdx.y * BM, bn = blockIdx.x * BN;
    int tx = threadIdx.x & 15, ty = threadIdx.x >> 4;

    float acc[4][4] = {};

    for (int k0 = 0; k0 < FK; k0 += BK) {
        // A tile: [BM rows][BK k], load float4 along k, store transposed
        #pragma unroll
        for (int l = 0; l < 2; l++) {
            int id = threadIdx.x + l * 256;          // 0..511
            int row = id >> 3;                       // 8 float4 per row
            int kk = (id & 7) << 2;
            float4 a = make_float4(0.f, 0.f, 0.f, 0.f);
            int gr = bm + row;
            if (gr < M) a = *(const float4*)&A[gr * FK + k0 + kk];
            As[kk + 0][row] = a.x; As[kk + 1][row] = a.y;
            As[kk + 2][row] = a.z; As[kk + 3][row] = a.w;
        }
        // B tile: [BK k][BN cols]
        #pragma unroll
        for (int l = 0; l < 2; l++) {
            int id = threadIdx.x + l * 256;
            int row = id >> 4;                       // 16 float4 per row
            int cc = (id & 15) << 2;
            float4 b = make_float4(0.f, 0.f, 0.f, 0.f);
            int gc = bn + cc;
            if (gc < Ncols) b = *(const float4*)&B[(k0 + row) * Ncols + gc];
            *(float4*)&Bs[row][cc] = b;
        }
        __syncthreads();

        #pragma unroll
        for (int k = 0; k < BK; k++) {
            float a[4], b[4];
            #pragma unroll
            for (int i = 0; i < 4; i++) a[i] = As[k][ty * 4 + i];
            #pragma unroll
            for (int j = 0; j < 4; j++) b[j] = Bs[k][tx * 4 + j];
            #pragma unroll
            for (int i = 0; i < 4; i++)
                #pragma unroll
                for (int j = 0; j < 4; j++)
                    acc[i][j] = fmaf(a[i], b[j], acc[i][j]);
        }
        __syncthreads();
    }

    #pragma unroll
    for (int i = 0; i < 4; i++) {
        int r = bm + ty * 4 + i;
        if (r >= M) continue;
        float di = g_dinv[r];
        #pragma unroll
        for (int j = 0; j < 4; j++) {
            int c = bn + tx * 4 + j;
            if (c >= Ncols) continue;
            float v = acc[i][j];
            if (mode == 1) {
                if (c < C1) {
                    float sv = di * v;
                    g_HS1[r * C1 + c] = sv;
                    g_S1[r * C1 + c] = sv;
                } else {
                    g_HSELF[r * C2 + (c - C1)] = v + bs[c - C1];
                }
            } else {
                float sv = di * v;
                g_HS2[r * C2 + c] = sv;
                g_S2[r * C2 + c] = sv;
            }
        }
    }
}

// ---------------- edge scatter: S[dst] += w * HS[src]  (float4 atomics) ------
template <int CHUNKS, int STRIDE>
__global__ __launch_bounds__(256) void k_scatter(const int* __restrict__ ei,
                                                 const float* __restrict__ ew,
                                                 const float* __restrict__ HS,
                                                 float* __restrict__ S) {
    long long gid = (long long)blockIdx.x * blockDim.x + threadIdx.x;
    if (gid >= (long long)EE * CHUNKS) return;
    int e = (int)(gid / CHUNKS);
    int c = (int)(gid - (long long)e * CHUNKS);
    int s = ei[e];
    int d = ei[EE + e];
    float w = ew[e];
    float4 v = *(const float4*)&HS[(long long)s * STRIDE + c * 4];
    v.x *= w; v.y *= w; v.z *= w; v.w *= w;
    atomicAdd((float4*)&S[(long long)d * STRIDE + c * 4], v);
}

// ---------------- finalize pass 1: bias/relu, leader gate, h_new -------------
__global__ __launch_bounds__(192) void k_finalize1(const float* __restrict__ b1,
                                                   const float* __restrict__ bl,
                                                   const float* __restrict__ Wl2,
                                                   const float* __restrict__ bl2,
                                                   float* __restrict__ out) {
    __shared__ float s_part[2];
    __shared__ float s_ls;
    int i = blockIdx.x;
    int t = threadIdx.x;
    float di = g_dinv[i];
    float hn = 0.0f;

    if (t < 128) {
        float v = di * g_S1[i * C1 + t] + b1[t];
        hn = fmaxf(v, 0.0f);
    } else {
        float v = di * g_S1[i * C1 + t] + bl[t - 128];
        float r = fmaxf(v, 0.0f);
        float p = r * Wl2[t - 128];
        #pragma unroll
        for (int o = 16; o > 0; o >>= 1)
            p += __shfl_down_sync(0xffffffffu, p, o);
        if ((t & 31) == 0) s_part[(t - 128) >> 5] = p;
    }
    __syncthreads();
    if (t == 0) {
        float z = s_part[0] + s_part[1] + bl2[0];
        float ls = 1.0f / (1.0f + expf(-z));
        s_ls = ls;
        out[NN * 128 + i] = ls;                // leader_score output
    }
    __syncthreads();
    if (t < 128) {
        float ls = s_ls;
        g_HNEW[i * C2 + t] = (1.0f - ls) * hn + ls * g_HSELF[i * C2 + t];
    }
}

// ---------------- finalize pass 2: h_final ----------------------------------
__global__ void k_finalize2(const float* __restrict__ b2,
                            float* __restrict__ out) {
    int idx = blockIdx.x * blockDim.x + threadIdx.x;
    if (idx >= NN * C2) return;
    int i = idx >> 7, c = idx & 127;
    float v = g_dinv[i] * g_S2[idx] + b2[c];
    out[idx] = fmaxf(v, 0.0f);
}

// ---------------- launch ------------------------------------------------------
extern "C" void kernel_launch(void* const* d_in, const int* in_sizes, int n_in,
                              void* d_out, int out_size) {
    const float* x   = (const float*)d_in[0];
    const int*   ei  = (const int*)d_in[1];        // int32! (JAX x64 disabled)
    const float* ew  = (const float*)d_in[2];
    const float* W1  = (const float*)d_in[3];
    const float* b1  = (const float*)d_in[4];
    const float* W2  = (const float*)d_in[5];
    const float* b2  = (const float*)d_in[6];
    const float* Ws  = (const float*)d_in[7];
    const float* bs  = (const float*)d_in[8];
    const float* Wl  = (const float*)d_in[9];
    const float* bl  = (const float*)d_in[10];
    const float* Wl2 = (const float*)d_in[11];
    const float* bl2 = (const float*)d_in[12];
    float* out = (float*)d_out;

    float* gWc;   cudaGetSymbolAddress((void**)&gWc,  g_Wc);
    float* gHS1;  cudaGetSymbolAddress((void**)&gHS1, g_HS1);
    float* gS1;   cudaGetSymbolAddress((void**)&gS1,  g_S1);
    float* gHNEW; cudaGetSymbolAddress((void**)&gHNEW, g_HNEW);
    float* gHS2;  cudaGetSymbolAddress((void**)&gHS2, g_HS2);
    float* gS2;   cudaGetSymbolAddress((void**)&gS2,  g_S2);

    // degree / dinv
    k_init_deg<<<(NN + 255) / 256, 256>>>();
    k_deg_accum<<<(EE + 255) / 256, 256>>>(ei, ew);
    k_dinv<<<(NN + 255) / 256, 256>>>();

    // fused weight
    k_build_wc<<<(FK * NC + 255) / 256, 256>>>(W1, Wl, Ws);

    // GEMM1: x @ [W1|Wl|Ws]  (epilogue: dinv-prescale + self-init / +bs)
    {
        dim3 grid(NC / BN, (NN + BM - 1) / BM);
        k_gemm<<<grid, 256>>>(x, gWc, NN, NC, 1, bs);
    }

    // scatter 1: 192 cols = 48 float4 chunks per edge
    {
        long long total = (long long)EE * 48;
        int blocks = (int)((total + 255) / 256);
        k_scatter<48, C1><<<blocks, 256>>>(ei, ew, gHS1, gS1);
    }

    // finalize 1: conv1 relu, leader score, gated h_new
    k_finalize1<<<NN, 192>>>(b1, bl, Wl2, bl2, out);

    // GEMM2: h_new @ W2 (epilogue: dinv-prescale + self-init)
    {
        dim3 grid(C2 / BN, (NN + BM - 1) / BM);
        k_gemm<<<grid, 256>>>(gHNEW, W2, NN, C2, 2, nullptr);
    }

    // scatter 2: 128 cols = 32 chunks
    {
        long long total = (long long)EE * 32;
        int blocks = (int)((total + 255) / 256);
        k_scatter<32, C2><<<blocks, 256>>>(ei, ew, gHS2, gS2);
    }

    // finalize 2: h_final
    k_finalize2<<<(NN * C2 + 255) / 256, 256>>>(b2, out);
}

// round 3
// speedup vs baseline: 1.3565x; 1.3565x over previous
#include <cuda_runtime.h>

#define NN 50000
#define EE 800000
#define FK 128          // inner dim
#define C1 192          // agg width pass 1 (128 conv1 + 64 leader)
#define C2 128          // agg width pass 2
#define NC 320          // fused GEMM1 cols: [W1(128) | Wl(64) | Ws(128)]
#define NB 196          // ceil(NN/256)

// ---------------- scratch (device globals; no allocations allowed) -----------
__device__ float g_deg[NN];
__device__ float g_dinv[NN];
__device__ int   g_cnt[NN];
__device__ int   g_rexcl[NN];
__device__ int   g_bsum[NB];
__device__ int   g_boff[NB];
__device__ int   g_rowptr[NN + 1];
__device__ int   g_pos[NN];
__device__ int   g_csr_src[EE];
__device__ float g_csr_w[EE];
__device__ float g_Wc[FK * NC];          // fused weight [128, 320]
__device__ float g_HS1[NN * C1];         // dinv-prescaled GEMM1 output
__device__ float g_HSELF[NN * C2];       // x@Ws + bs
__device__ float g_HNEW[NN * C2];        // gated fusion
__device__ float g_HS2[NN * C2];         // dinv-prescaled GEMM2 output

// ---------------- f32x2 packed helpers ---------------------------------------
typedef unsigned long long u64;
__device__ __forceinline__ u64 pack_dup(float a) {
    u64 r;
    asm("mov.b64 %0, {%1, %1};" : "=l"(r) : "f"(a));
    return r;
}
__device__ __forceinline__ void fma2(u64& d, u64 a, u64 b) {
    asm("fma.rn.f32x2 %0, %1, %2, %0;" : "+l"(d) : "l"(a), "l"(b));
}
__device__ __forceinline__ void unpack2(u64 v, float& lo, float& hi) {
    asm("mov.b64 {%0, %1}, %2;" : "=f"(lo), "=f"(hi) : "l"(v));
}

// ---------------- degree / histogram -----------------------------------------
__global__ void k_init() {
    int i = blockIdx.x * blockDim.x + threadIdx.x;
    if (i < NN) { g_deg[i] = 1.0f; g_cnt[i] = 0; }     // self-loop weight 1
}

__global__ void k_deg_hist(const int* __restrict__ ei,
                           const float* __restrict__ ew) {
    int e = blockIdx.x * blockDim.x + threadIdx.x;
    if (e < EE) {
        int d = ei[EE + e];
        atomicAdd(&g_deg[d], ew[e]);
        atomicAdd(&g_cnt[d], 1);
    }
}

__global__ void k_dinv() {
    int i = blockIdx.x * blockDim.x + threadIdx.x;
    if (i < NN) {
        float dg = g_deg[i];
        g_dinv[i] = dg > 0.0f ? rsqrtf(dg) : 0.0f;
    }
}

// ---------------- hierarchical exclusive scan of g_cnt -----------------------
__device__ __forceinline__ int block_scan256(int v, int t, int* total) {
    int lane = t & 31, w = t >> 5;
    int x = v;
    #pragma unroll
    for (int o = 1; o < 32; o <<= 1) {
        int y = __shfl_up_sync(0xffffffffu, x, o);
        if (lane >= o) x += y;
    }
    __shared__ int ws[8];
    if (lane == 31) ws[w] = x;
    __syncthreads();
    if (t < 8) {
        int z = ws[t];
        #pragma unroll
        for (int o = 1; o < 8; o <<= 1) {
            int q = __shfl_up_sync(0xffu, z, o);
            if (t >= o) z += q;
        }
        ws[t] = z;
    }
    __syncthreads();
    int woff = (w > 0) ? ws[w - 1] : 0;
    *total = ws[7];
    return woff + x - v;           // exclusive prefix
}

__global__ __launch_bounds__(256) void kA_scan() {
    int b = blockIdx.x, t = threadIdx.x;
    int i = b * 256 + t;
    int v = (i < NN) ? g_cnt[i] : 0;
    int total;
    int excl = block_scan256(v, t, &total);
    if (i < NN) g_rexcl[i] = excl;
    if (t == 0) g_bsum[b] = total;
}

__global__ __launch_bounds__(256) void kB_scan() {
    int t = threadIdx.x;
    int v = (t < NB) ? g_bsum[t] : 0;
    int total;
    int excl = block_scan256(v, t, &total);
    if (t < NB) g_boff[t] = excl;
}

__global__ void kC_finalize_ptr() {
    int i = blockIdx.x * blockDim.x + threadIdx.x;
    if (i < NN) {
        int r = g_rexcl[i] + g_boff[i >> 8];
        g_rowptr[i] = r;
        g_pos[i] = r;
    }
    if (i == NN) g_rowptr[NN] = EE;
}

__global__ void k_fill(const int* __restrict__ ei,
                       const float* __restrict__ ew) {
    int e = blockIdx.x * blockDim.x + threadIdx.x;
    if (e < EE) {
        int d = ei[EE + e];
        int p = atomicAdd(&g_pos[d], 1);
        g_csr_src[p] = ei[e];
        g_csr_w[p] = ew[e];
    }
}

// ---------------- fused weight -----------------------------------------------
__global__ void k_build_wc(const float* __restrict__ W1,
                           const float* __restrict__ Wl,
                           const float* __restrict__ Ws) {
    int idx = blockIdx.x * blockDim.x + threadIdx.x;
    if (idx >= FK * NC) return;
    int k = idx / NC, c = idx % NC;
    float v;
    if (c < 128)       v = W1[k * 128 + c];
    else if (c < 192)  v = Wl[k * 64 + (c - 128)];
    else               v = Ws[k * 128 + (c - 192)];
    g_Wc[idx] = v;
}

// ---------------- GEMM with packed f32x2 FMA ---------------------------------
// mode 1: c<192 -> HS1 = dinv*v ; c>=192 -> HSELF = v + bs
// mode 2: HS2 = dinv*v
#define BM 64
#define BN 64
#define BK 32
__global__ __launch_bounds__(256) void k_gemm(const float* __restrict__ A,
                                              const float* __restrict__ B,
                                              int M, int Ncols, int mode,
                                              const float* __restrict__ bs) {
    __shared__ float As[BK][BM + 1];
    __shared__ __align__(16) float Bs[BK][BN];
    int bm = blockIdx.y * BM, bn = blockIdx.x * BN;
    int tx = threadIdx.x & 15, ty = threadIdx.x >> 4;

    u64 acc2[4][2];
    #pragma unroll
    for (int i = 0; i < 4; i++) { acc2[i][0] = 0ull; acc2[i][1] = 0ull; }

    for (int k0 = 0; k0 < FK; k0 += BK) {
        #pragma unroll
        for (int l = 0; l < 2; l++) {
            int id = threadIdx.x + l * 256;
            int row = id >> 3;
            int kk = (id & 7) << 2;
            float4 a = make_float4(0.f, 0.f, 0.f, 0.f);
            int gr = bm + row;
            if (gr < M) a = *(const float4*)&A[gr * FK + k0 + kk];
            As[kk + 0][row] = a.x; As[kk + 1][row] = a.y;
            As[kk + 2][row] = a.z; As[kk + 3][row] = a.w;
        }
        #pragma unroll
        for (int l = 0; l < 2; l++) {
            int id = threadIdx.x + l * 256;
            int row = id >> 4;
            int cc = (id & 15) << 2;
            float4 b = make_float4(0.f, 0.f, 0.f, 0.f);
            int gc = bn + cc;
            if (gc < Ncols) b = *(const float4*)&B[(k0 + row) * Ncols + gc];
            *(float4*)&Bs[row][cc] = b;
        }
        __syncthreads();

        #pragma unroll
        for (int k = 0; k < BK; k++) {
            u64 b0 = *(const u64*)&Bs[k][tx * 4];
            u64 b1 = *(const u64*)&Bs[k][tx * 4 + 2];
            #pragma unroll
            for (int i = 0; i < 4; i++) {
                u64 ap = pack_dup(As[k][ty * 4 + i]);
                fma2(acc2[i][0], ap, b0);
                fma2(acc2[i][1], ap, b1);
            }
        }
        __syncthreads();
    }

    #pragma unroll
    for (int i = 0; i < 4; i++) {
        int r = bm + ty * 4 + i;
        if (r >= M) continue;
        float di = g_dinv[r];
        #pragma unroll
        for (int j2 = 0; j2 < 2; j2++) {
            float v0, v1;
            unpack2(acc2[i][j2], v0, v1);
            int c = bn + tx * 4 + j2 * 2;
            float vv[2] = {v0, v1};
            #pragma unroll
            for (int q = 0; q < 2; q++) {
                int cc = c + q;
                if (cc >= Ncols) continue;
                float v = vv[q];
                if (mode == 1) {
                    if (cc < C1) g_HS1[r * C1 + cc] = di * v;
                    else         g_HSELF[r * C2 + (cc - C1)] = v + bs[cc - C1];
                } else {
                    g_HS2[r * C2 + cc] = di * v;
                }
            }
        }
    }
}

// ---------------- gather pass 1: agg + conv1 relu + leader + gate ------------
__global__ __launch_bounds__(192) void k_gather1(const float* __restrict__ b1,
                                                 const float* __restrict__ bl,
                                                 const float* __restrict__ Wl2,
                                                 const float* __restrict__ bl2,
                                                 float* __restrict__ out) {
    __shared__ int   s_src[192];
    __shared__ float s_w[192];
    __shared__ float s_part[2];
    __shared__ float s_ls;
    int row = blockIdx.x;
    int t = threadIdx.x;
    int beg = g_rowptr[row], end = g_rowptr[row + 1];

    float acc = g_HS1[row * C1 + t];           // self term (dinv-prescaled)
    for (int chunk = beg; chunk < end; chunk += 192) {
        int m = min(192, end - chunk);
        __syncthreads();
        if (t < m) { s_src[t] = g_csr_src[chunk + t]; s_w[t] = g_csr_w[chunk + t]; }
        __syncthreads();
        #pragma unroll 4
        for (int j = 0; j < m; j++)
            acc = fmaf(s_w[j], g_HS1[s_src[j] * C1 + t], acc);
    }

    float di = g_dinv[row];
    if (t >= 128) {                            // leader branch (warps 4,5)
        float r = fmaxf(di * acc + bl[t - 128], 0.0f);
        float p = r * Wl2[t - 128];
        #pragma unroll
        for (int o = 16; o > 0; o >>= 1)
            p += __shfl_down_sync(0xffffffffu, p, o);
        if ((t & 31) == 0) s_part[(t - 128) >> 5] = p;
    }
    __syncthreads();
    if (t == 0) {
        float z = s_part[0] + s_part[1] + bl2[0];
        float ls = 1.0f / (1.0f + expf(-z));
        s_ls = ls;
        out[NN * 128 + row] = ls;              // leader_score output
    }
    __syncthreads();
    if (t < 128) {
        float hn = fmaxf(di * acc + b1[t], 0.0f);
        float ls = s_ls;
        g_HNEW[row * C2 + t] = (1.0f - ls) * hn + ls * g_HSELF[row * C2 + t];
    }
}

// ---------------- gather pass 2: agg + final relu ----------------------------
__global__ __launch_bounds__(128) void k_gather2(const float* __restrict__ b2,
                                                 float* __restrict__ out) {
    __shared__ int   s_src[128];
    __shared__ float s_w[128];
    int row = blockIdx.x;
    int t = threadIdx.x;
    int beg = g_rowptr[row], end = g_rowptr[row + 1];

    float acc = g_HS2[row * C2 + t];
    for (int chunk = beg; chunk < end; chunk += 128) {
        int m = min(128, end - chunk);
        __syncthreads();
        if (t < m) { s_src[t] = g_csr_src[chunk + t]; s_w[t] = g_csr_w[chunk + t]; }
        __syncthreads();
        #pragma unroll 4
        for (int j = 0; j < m; j++)
            acc = fmaf(s_w[j], g_HS2[s_src[j] * C2 + t], acc);
    }
    out[row * C2 + t] = fmaxf(g_dinv[row] * acc + b2[t], 0.0f);
}

// ---------------- launch ------------------------------------------------------
extern "C" void kernel_launch(void* const* d_in, const int* in_sizes, int n_in,
                              void* d_out, int out_size) {
    const float* x   = (const float*)d_in[0];
    const int*   ei  = (const int*)d_in[1];        // int32 (JAX x64 disabled)
    const float* ew  = (const float*)d_in[2];
    const float* W1  = (const float*)d_in[3];
    const float* b1  = (const float*)d_in[4];
    const float* W2  = (const float*)d_in[5];
    const float* b2  = (const float*)d_in[6];
    const float* Ws  = (const float*)d_in[7];
    const float* bs  = (const float*)d_in[8];
    const float* Wl  = (const float*)d_in[9];
    const float* bl  = (const float*)d_in[10];
    const float* Wl2 = (const float*)d_in[11];
    const float* bl2 = (const float*)d_in[12];
    float* out = (float*)d_out;

    float* gWc;   cudaGetSymbolAddress((void**)&gWc,  g_Wc);
    float* gHNEW; cudaGetSymbolAddress((void**)&gHNEW, g_HNEW);

    // degree + histogram + dinv
    k_init<<<(NN + 255) / 256, 256>>>();
    k_deg_hist<<<(EE + 255) / 256, 256>>>(ei, ew);
    k_dinv<<<(NN + 255) / 256, 256>>>();

    // CSR build
    kA_scan<<<NB, 256>>>();
    kB_scan<<<1, 256>>>();
    kC_finalize_ptr<<<(NN + 256) / 256, 256>>>();
    k_fill<<<(EE + 255) / 256, 256>>>(ei, ew);

    // fused weight
    k_build_wc<<<(FK * NC + 255) / 256, 256>>>(W1, Wl, Ws);

    // GEMM1: x @ [W1|Wl|Ws]
    {
        dim3 grid(NC / BN, (NN + BM - 1) / BM);
        k_gemm<<<grid, 256>>>(x, gWc, NN, NC, 1, bs);
    }

    // gather 1 (fused finalize: relu, leader score, gate)
    k_gather1<<<NN, 192>>>(b1, bl, Wl2, bl2, out);

    // GEMM2: h_new @ W2
    {
        dim3 grid(C2 / BN, (NN + BM - 1) / BM);
        k_gemm<<<grid, 256>>>(gHNEW, W2, NN, C2, 2, nullptr);
    }

    // gather 2 (fused final relu)
    k_gather2<<<NN, 128>>>(b2, out);
}